// round 16
// baseline (speedup 1.0000x reference)
#include <cuda_runtime.h>
#include <cuda_fp16.h>
#include <math.h>
#include <stdint.h>

#define S_LEN 2048
#define BATCH 2
#define EMB   1024
#define NHEAD 16
#define HDIM  64
#define MROWS (BATCH * S_LEN)                  /* 4096 */
#define OUT_ELEMS (MROWS * EMB)                /* 4194304 */
#define W_ELEMS ((size_t)BATCH * NHEAD * S_LEN * S_LEN) /* 134217728 */
// 0.125 * log2(e): folded into Q columns in the QKV-GEMM epilogue
#define Q_PRESCALE 0.18033688f

// f4-unit sizes for the merged convert kernel
#define Q4  (OUT_ELEMS / 4)                    /* 1048576 */
#define WI4 (3 * EMB * EMB / 4)                /* 786432 */
#define WO4 (EMB * EMB / 4)                    /* 262144 */

// ---------------- scratch (static device globals; no runtime alloc) --------
__device__ __half g_q16[MROWS * EMB];
__device__ __half g_wi16[3 * EMB * EMB];
__device__ __half g_wo16[EMB * EMB];
__device__ __half g_qkv16[MROWS * 3 * EMB];
__device__ __half g_ao16[MROWS * EMB];
__device__ float  g_attnw_fallback[BATCH * NHEAD * S_LEN * S_LEN];

// ---------------- ptx helpers ----------------------------------------------
__device__ __forceinline__ uint32_t smem_u32(const void* p) {
    return (uint32_t)__cvta_generic_to_shared(p);
}

__device__ __forceinline__ void ldsm_x4(uint32_t addr, uint32_t& r0, uint32_t& r1,
                                        uint32_t& r2, uint32_t& r3) {
    asm volatile("ldmatrix.sync.aligned.m8n8.x4.shared.b16 {%0,%1,%2,%3}, [%4];"
                 : "=r"(r0), "=r"(r1), "=r"(r2), "=r"(r3) : "r"(addr));
}

__device__ __forceinline__ void ldsm_x4_t(uint32_t addr, uint32_t& r0, uint32_t& r1,
                                          uint32_t& r2, uint32_t& r3) {
    asm volatile("ldmatrix.sync.aligned.m8n8.x4.trans.shared.b16 {%0,%1,%2,%3}, [%4];"
                 : "=r"(r0), "=r"(r1), "=r"(r2), "=r"(r3) : "r"(addr));
}

__device__ __forceinline__ void mma16816(float* c, const uint32_t* a, uint32_t b0, uint32_t b1) {
    asm volatile(
        "mma.sync.aligned.m16n8k16.row.col.f32.f16.f16.f32 "
        "{%0,%1,%2,%3}, {%4,%5,%6,%7}, {%8,%9}, {%0,%1,%2,%3};"
        : "+f"(c[0]), "+f"(c[1]), "+f"(c[2]), "+f"(c[3])
        : "r"(a[0]), "r"(a[1]), "r"(a[2]), "r"(a[3]), "r"(b0), "r"(b1));
}

__device__ __forceinline__ uint32_t pack_h2(float x, float y) {
    __half2 h = __floats2half2_rn(x, y);
    return *reinterpret_cast<uint32_t*>(&h);
}

__device__ __forceinline__ float ex2f(float x) {
    float y;
    asm("ex2.approx.ftz.f32 %0, %1;" : "=f"(y) : "f"(x));
    return y;
}

__device__ __forceinline__ void cp16(uint32_t dst_smem, const void* src) {
    asm volatile("cp.async.cg.shared.global [%0], [%1], 16;" :: "r"(dst_smem), "l"(src));
}
#define CP_COMMIT() asm volatile("cp.async.commit_group;")
#define CP_WAIT1()  asm volatile("cp.async.wait_group 1;")

// ---------------- merged f32 -> f16 convert (q, in_w, out_w in one launch) --
__global__ void f2h_all_kernel(const float4* __restrict__ q,
                               const float4* __restrict__ wi,
                               const float4* __restrict__ wo,
                               __half* __restrict__ q16,
                               __half* __restrict__ wi16,
                               __half* __restrict__ wo16) {
    int i = blockIdx.x * blockDim.x + threadIdx.x;
    const float4* src;
    __half* dst;
    int j;
    if (i < Q4)            { src = q;  dst = q16;  j = i; }
    else if (i < Q4 + WI4) { src = wi; dst = wi16; j = i - Q4; }
    else if (i < Q4 + WI4 + WO4) { src = wo; dst = wo16; j = i - Q4 - WI4; }
    else return;
    float4 f = src[j];
    __half2* d = (__half2*)(dst + (size_t)j * 4);
    d[0] = __floats2half2_rn(f.x, f.y);
    d[1] = __floats2half2_rn(f.z, f.w);
}

// ---------------------------------------------------------------------------
// GEMM: C[M,N] = A16[M,K] @ W16[N,K]^T + bias.  128x128 tile, BK=64,
// 256 threads = 8 warps (2m x 4n), warp tile 64x32, mma.m16n8k16.
// 3-stage cp.async pipeline; smem = 3 * 32 KB = 96 KB dynamic.
// ---------------------------------------------------------------------------
template <bool OUT_HALF>
__global__ __launch_bounds__(256, 2) void gemm16_kernel(
    const __half* __restrict__ A, const __half* __restrict__ W,
    const float* __restrict__ bias, void* __restrict__ Cout,
    int M, int N, int K)
{
    extern __shared__ __half sm[];
    const int tid = threadIdx.x;
    const int lane = tid & 31, wid = tid >> 5;
    const int wm = wid >> 2, wn = wid & 3;
    const int m0 = blockIdx.y * 128, n0 = blockIdx.x * 128;

    float acc[4][4][4];
#pragma unroll
    for (int i = 0; i < 4; i++)
#pragma unroll
        for (int j = 0; j < 4; j++)
#pragma unroll
            for (int r = 0; r < 4; r++) acc[i][j][r] = 0.0f;

    auto prefetch = [&](int k0, int s) {
#pragma unroll
        for (int i = 0; i < 4; i++) {
            int cid = tid + 256 * i;       // 0..1023
            int row = cid >> 3;            // 0..127
            int ch  = cid & 7;             // 0..7
            int sw  = (ch ^ (row & 7)) * 8;
            cp16(smem_u32(sm + s * 8192 + row * 64 + sw),
                 A + (size_t)(m0 + row) * K + k0 + ch * 8);
            cp16(smem_u32(sm + 24576 + s * 8192 + row * 64 + sw),
                 W + (size_t)(n0 + row) * K + k0 + ch * 8);
        }
    };

    const int nk = K / 64;
    prefetch(0, 0); CP_COMMIT();
    prefetch(64, 1); CP_COMMIT();

    for (int t = 0; t < nk; t++) {
        CP_WAIT1();
        __syncthreads();
        if (t + 2 < nk) prefetch((t + 2) * 64, (t + 2) % 3);
        CP_COMMIT();

        const __half* As = sm + (t % 3) * 8192;
        const __half* Bs = sm + 24576 + (t % 3) * 8192;

#pragma unroll
        for (int ks = 0; ks < 4; ks++) {
            uint32_t a[4][4];
#pragma unroll
            for (int mt = 0; mt < 4; mt++) {
                int row = wm * 64 + mt * 16 + (lane & 15);
                int kk = ks * 16 + (lane >> 4) * 8;
                int ch = (kk >> 3) ^ (row & 7);
                ldsm_x4(smem_u32(As + row * 64 + ch * 8), a[mt][0], a[mt][1], a[mt][2], a[mt][3]);
            }
#pragma unroll
            for (int ntp = 0; ntp < 2; ntp++) {
                int row = wn * 32 + ntp * 16 + ((lane >> 4) & 1) * 8 + (lane & 7);
                int kk = ks * 16 + ((lane >> 3) & 1) * 8;
                int ch = (kk >> 3) ^ (row & 7);
                uint32_t b0, b1, b2, b3;
                ldsm_x4(smem_u32(Bs + row * 64 + ch * 8), b0, b1, b2, b3);
#pragma unroll
                for (int mt = 0; mt < 4; mt++) {
                    mma16816(acc[mt][2 * ntp], a[mt], b0, b1);
                    mma16816(acc[mt][2 * ntp + 1], a[mt], b2, b3);
                }
            }
        }
    }

    // epilogue
    const int g = lane >> 2, qd = lane & 3;
#pragma unroll
    for (int mt = 0; mt < 4; mt++) {
#pragma unroll
        for (int nt = 0; nt < 4; nt++) {
            int row = m0 + wm * 64 + mt * 16 + g;
            int col = n0 + wn * 32 + nt * 8 + 2 * qd;
            float b0 = bias[col], b1 = bias[col + 1];
            float v0 = acc[mt][nt][0] + b0, v1 = acc[mt][nt][1] + b1;
            float v2 = acc[mt][nt][2] + b0, v3 = acc[mt][nt][3] + b1;
            if (OUT_HALF) {
                float qs = (col < EMB) ? Q_PRESCALE : 1.0f;   // Q columns of QKV
                v0 *= qs; v1 *= qs; v2 *= qs; v3 *= qs;
                __half* C = (__half*)Cout;
                *(__half2*)(C + (size_t)row * N + col) = __floats2half2_rn(v0, v1);
                *(__half2*)(C + (size_t)(row + 8) * N + col) = __floats2half2_rn(v2, v3);
            } else {
                float* C = (float*)Cout;
                *(float2*)(C + (size_t)row * N + col) = make_float2(v0, v1);
                *(float2*)(C + (size_t)(row + 8) * N + col) = make_float2(v2, v3);
            }
        }
    }
}

// ---------------------------------------------------------------------------
// Fused attention: block = (q-tile of 128, one (b,h)).  8 warps x 16 q-rows.
// Q pre-scaled by 0.125*log2e -> QK^T accumulators are log2-domain scores.
// pass1: s_row = sum ex2(acc);  pass2: w = ex2(acc - log2(s_row)) -> P@V.
// 4-stage cp.async rings (reuse distance 4) -> __syncthreads only every 2
// iterations (sync at even jt covers the prefetches of jt and jt+1).
// smem: Q 16KB + 4x8KB K + 4x8KB V = 80 KB (2 CTAs/SM: 160 <= 227KB).
// ---------------------------------------------------------------------------
__global__ __launch_bounds__(256, 2) void attn16_kernel(
    const __half* __restrict__ qkv, float* __restrict__ attnw,
    __half* __restrict__ aout, int write_w)
{
    extern __shared__ __half sm[];
    __half* Qs = sm;                 // [128][64]
    __half* KsB = sm + 8192;         // 4 x [64][64]
    __half* VsB = sm + 24576;        // 4 x [64][64]

    const int tid = threadIdx.x;
    const int lane = tid & 31, wid = tid >> 5;
    const int qt = blockIdx.x, bh = blockIdx.y;
    const int b = bh >> 4, h = bh & 15;
    const int rowbase = b * S_LEN;
    const int q0 = qt * 128;
    const int stride = 3 * EMB;
    const int g = lane >> 2, qd = lane & 3;
    const int NJT = S_LEN / 64;

    auto pre_k = [&](int jt, int s) {
#pragma unroll
        for (int i = 0; i < 2; i++) {
            int cid = tid + 256 * i;
            int row = cid >> 3, ch = cid & 7;
            cp16(smem_u32(KsB + s * 4096 + row * 64 + (ch ^ (row & 7)) * 8),
                 qkv + (size_t)(rowbase + jt * 64 + row) * stride + EMB + h * HDIM + ch * 8);
        }
    };
    auto pre_kv = [&](int jt, int s) {
#pragma unroll
        for (int i = 0; i < 2; i++) {
            int cid = tid + 256 * i;
            int row = cid >> 3, ch = cid & 7;
            const __half* src = qkv + (size_t)(rowbase + jt * 64 + row) * stride + h * HDIM + ch * 8;
            uint32_t sw = (ch ^ (row & 7)) * 8;
            cp16(smem_u32(KsB + s * 4096 + row * 64 + sw), src + EMB);
            cp16(smem_u32(VsB + s * 4096 + row * 64 + sw), src + 2 * EMB);
        }
    };

    // load Q tile (128 x 64 halves), swizzled
#pragma unroll
    for (int i = 0; i < 4; i++) {
        int cid = tid + 256 * i;
        int row = cid >> 3, ch = cid & 7;
        *(uint4*)&Qs[row * 64 + (ch ^ (row & 7)) * 8] =
            *(const uint4*)(qkv + (size_t)(rowbase + q0 + row) * stride + h * HDIM + ch * 8);
    }
    __syncthreads();

    // issue first two K-stage prefetches BEFORE the Q-frag LDSM (overlap)
    pre_k(0, 0); CP_COMMIT();
    pre_k(1, 1); CP_COMMIT();

    // Q fragments (persist across both passes)
    uint32_t qa[4][4];
#pragma unroll
    for (int ks = 0; ks < 4; ks++) {
        int row = wid * 16 + (lane & 15);
        int kk = ks * 16 + (lane >> 4) * 8;
        int ch = (kk >> 3) ^ (row & 7);
        ldsm_x4(smem_u32(Qs + row * 64 + ch * 8), qa[ks][0], qa[ks][1], qa[ks][2], qa[ks][3]);
    }

    float s0r = 0.0f, s1r = 0.0f;

    // ---------------- pass 1: denominators ----------------
    for (int jt = 0; jt < NJT; jt++) {
        CP_WAIT1();
        if ((jt & 1) == 0) __syncthreads();     // covers prefetch of jt, jt+1
        if (jt + 2 < NJT) pre_k(jt + 2, (jt + 2) & 3);
        CP_COMMIT();
        const __half* Ks = KsB + (jt & 3) * 4096;

        float sc[8][4];
#pragma unroll
        for (int t = 0; t < 8; t++)
#pragma unroll
            for (int r = 0; r < 4; r++) sc[t][r] = 0.0f;

#pragma unroll
        for (int ks = 0; ks < 4; ks++) {
#pragma unroll
            for (int ntp = 0; ntp < 4; ntp++) {
                int row = ntp * 16 + ((lane >> 4) & 1) * 8 + (lane & 7);
                int kk = ks * 16 + ((lane >> 3) & 1) * 8;
                int ch = (kk >> 3) ^ (row & 7);
                uint32_t b0, b1, b2, b3;
                ldsm_x4(smem_u32(Ks + row * 64 + ch * 8), b0, b1, b2, b3);
                mma16816(sc[2 * ntp], qa[ks], b0, b1);
                mma16816(sc[2 * ntp + 1], qa[ks], b2, b3);
            }
        }

        float p0 = 0.0f, p1 = 0.0f;
#pragma unroll
        for (int t = 0; t < 8; t++) {
            p0 += ex2f(sc[t][0]) + ex2f(sc[t][1]);
            p1 += ex2f(sc[t][2]) + ex2f(sc[t][3]);
        }
        s0r += p0;
        s1r += p1;
    }

    // stages 0,1 were last read at jt=28,29 — the jt=30 sync guarantees all
    // warps are past them.  Prefetch pass-2 tiles 0,1 NOW, overlapping the
    // cross-lane reduction + log2 below (no extra barrier needed).
    pre_kv(0, 0); CP_COMMIT();
    pre_kv(1, 1); CP_COMMIT();

    s0r += __shfl_xor_sync(0xffffffffu, s0r, 1);
    s0r += __shfl_xor_sync(0xffffffffu, s0r, 2);
    s1r += __shfl_xor_sync(0xffffffffu, s1r, 1);
    s1r += __shfl_xor_sync(0xffffffffu, s1r, 2);

    const float c0 = -__log2f(s0r);
    const float c1 = -__log2f(s1r);

    // ---------------- pass 2: weights + P@V ----------------
    float oacc[8][4];
#pragma unroll
    for (int t = 0; t < 8; t++)
#pragma unroll
        for (int r = 0; r < 4; r++) oacc[t][r] = 0.0f;

    float* wbase0 = attnw + ((size_t)bh * S_LEN + q0 + wid * 16) * S_LEN;

    for (int jt = 0; jt < NJT; jt++) {
        CP_WAIT1();
        if ((jt & 1) == 0) __syncthreads();     // jt=0 sync also closes pass-1 skew
        if (jt + 2 < NJT) pre_kv(jt + 2, (jt + 2) & 3);
        CP_COMMIT();
        const __half* Ks = KsB + (jt & 3) * 4096;
        const __half* Vs = VsB + (jt & 3) * 4096;

        float sc[8][4];
#pragma unroll
        for (int t = 0; t < 8; t++)
#pragma unroll
            for (int r = 0; r < 4; r++) sc[t][r] = 0.0f;

#pragma unroll
        for (int ks = 0; ks < 4; ks++) {
#pragma unroll
            for (int ntp = 0; ntp < 4; ntp++) {
                int row = ntp * 16 + ((lane >> 4) & 1) * 8 + (lane & 7);
                int kk = ks * 16 + ((lane >> 3) & 1) * 8;
                int ch = (kk >> 3) ^ (row & 7);
                uint32_t b0, b1, b2, b3;
                ldsm_x4(smem_u32(Ks + row * 64 + ch * 8), b0, b1, b2, b3);
                mma16816(sc[2 * ntp], qa[ks], b0, b1);
                mma16816(sc[2 * ntp + 1], qa[ks], b2, b3);
            }
        }

        // normalized weights: f32 streaming store (if live) + f16 A-frag pack
        uint32_t pa[4][4];
#pragma unroll
        for (int t = 0; t < 8; t++) {
            float w0 = ex2f(sc[t][0] + c0);
            float w1 = ex2f(sc[t][1] + c0);
            float w2 = ex2f(sc[t][2] + c1);
            float w3 = ex2f(sc[t][3] + c1);
            if (write_w) {
                float* wp = wbase0 + (size_t)g * S_LEN + jt * 64 + t * 8 + 2 * qd;
                __stcs((float2*)wp, make_float2(w0, w1));
                __stcs((float2*)(wp + 8 * S_LEN), make_float2(w2, w3));
            }
            pa[t >> 1][(t & 1) * 2 + 0] = pack_h2(w0, w1);
            pa[t >> 1][(t & 1) * 2 + 1] = pack_h2(w2, w3);
        }

        // P @ V
#pragma unroll
        for (int ks2 = 0; ks2 < 4; ks2++) {
#pragma unroll
            for (int dtp = 0; dtp < 4; dtp++) {
                int jrow = ks2 * 16 + ((lane >> 3) & 1) * 8 + (lane & 7);
                int dt = dtp * 2 + ((lane >> 4) & 1);
                int ch = dt ^ (jrow & 7);
                uint32_t b0, b1, b2, b3;
                ldsm_x4_t(smem_u32(Vs + jrow * 64 + ch * 8), b0, b1, b2, b3);
                mma16816(oacc[2 * dtp], pa[ks2], b0, b1);
                mma16816(oacc[2 * dtp + 1], pa[ks2], b2, b3);
            }
        }
    }

    // write attn_out (f16, [B*S, E], head slice)
#pragma unroll
    for (int dt = 0; dt < 8; dt++) {
        int row = rowbase + q0 + wid * 16 + g;
        int col = h * HDIM + dt * 8 + 2 * qd;
        *(__half2*)(aout + (size_t)row * EMB + col) = __floats2half2_rn(oacc[dt][0], oacc[dt][1]);
        *(__half2*)(aout + (size_t)(row + 8) * EMB + col) = __floats2half2_rn(oacc[dt][2], oacc[dt][3]);
    }
}

// ---------------------------------------------------------------------------
extern "C" void kernel_launch(void* const* d_in, const int* in_sizes, int n_in,
                              void* d_out, int out_size)
{
    const float* query = (const float*)d_in[0];
    const float* in_w  = (const float*)d_in[3];
    const float* in_b  = (const float*)d_in[4];
    const float* out_w = (const float*)d_in[5];
    const float* out_b = (const float*)d_in[6];
    float* out = (float*)d_out;

    __half *q16, *wi16, *wo16, *qkv16, *ao16;
    float* wfall;
    cudaGetSymbolAddress((void**)&q16, g_q16);
    cudaGetSymbolAddress((void**)&wi16, g_wi16);
    cudaGetSymbolAddress((void**)&wo16, g_wo16);
    cudaGetSymbolAddress((void**)&qkv16, g_qkv16);
    cudaGetSymbolAddress((void**)&ao16, g_ao16);
    cudaGetSymbolAddress((void**)&wfall, g_attnw_fallback);

    const int weights_live = ((size_t)out_size >= (size_t)OUT_ELEMS + W_ELEMS) ? 1 : 0;
    float* attnw = weights_live ? (out + OUT_ELEMS) : wfall;

    cudaFuncSetAttribute(gemm16_kernel<true>, cudaFuncAttributeMaxDynamicSharedMemorySize, 98304);
    cudaFuncSetAttribute(gemm16_kernel<false>, cudaFuncAttributeMaxDynamicSharedMemorySize, 98304);
    cudaFuncSetAttribute(attn16_kernel, cudaFuncAttributeMaxDynamicSharedMemorySize, 81920);

    // single merged f32 -> f16 convert (q + in_w + out_w)
    f2h_all_kernel<<<(Q4 + WI4 + WO4 + 255) / 256, 256>>>(
        (const float4*)query, (const float4*)in_w, (const float4*)out_w,
        q16, wi16, wo16);

    // QKV projection -> f16 (Q columns pre-scaled to log2 domain)
    gemm16_kernel<true><<<dim3(3 * EMB / 128, MROWS / 128), 256, 98304>>>(
        q16, wi16, in_b, qkv16, MROWS, 3 * EMB, EMB);

    // fused attention (weights f32 only when live + attn_out f16)
    attn16_kernel<<<dim3(S_LEN / 128, BATCH * NHEAD), 256, 81920>>>(
        qkv16, attnw, ao16, weights_live);

    // output projection -> f32
    gemm16_kernel<false><<<dim3(EMB / 128, MROWS / 128), 256, 98304>>>(
        ao16, wo16, out_b, out, MROWS, EMB, EMB);
}

// round 17
// speedup vs baseline: 1.0191x; 1.0191x over previous
#include <cuda_runtime.h>
#include <cuda_fp16.h>
#include <math.h>
#include <stdint.h>

#define S_LEN 2048
#define BATCH 2
#define EMB   1024
#define NHEAD 16
#define HDIM  64
#define MROWS (BATCH * S_LEN)                  /* 4096 */
#define OUT_ELEMS (MROWS * EMB)                /* 4194304 */
#define W_ELEMS ((size_t)BATCH * NHEAD * S_LEN * S_LEN) /* 134217728 */
// 0.125 * log2(e): folded into Q columns in the QKV-GEMM epilogue
#define Q_PRESCALE 0.18033688f

// f4-unit sizes for the merged convert kernel
#define Q4  (OUT_ELEMS / 4)                    /* 1048576 */
#define WI4 (3 * EMB * EMB / 4)                /* 786432 */
#define WO4 (EMB * EMB / 4)                    /* 262144 */
#define TOT4 (Q4 + WI4 + WO4)

// ---------------- scratch (static device globals; no runtime alloc) --------
__device__ __half g_q16[MROWS * EMB];
__device__ __half g_wi16[3 * EMB * EMB];
__device__ __half g_wo16[EMB * EMB];
__device__ __half g_qkv16[MROWS * 3 * EMB];
__device__ __half g_ao16[MROWS * EMB];
__device__ float  g_attnw_fallback[BATCH * NHEAD * S_LEN * S_LEN];

// ---------------- ptx helpers ----------------------------------------------
__device__ __forceinline__ uint32_t smem_u32(const void* p) {
    return (uint32_t)__cvta_generic_to_shared(p);
}

__device__ __forceinline__ void ldsm_x4(uint32_t addr, uint32_t& r0, uint32_t& r1,
                                        uint32_t& r2, uint32_t& r3) {
    asm volatile("ldmatrix.sync.aligned.m8n8.x4.shared.b16 {%0,%1,%2,%3}, [%4];"
                 : "=r"(r0), "=r"(r1), "=r"(r2), "=r"(r3) : "r"(addr));
}

__device__ __forceinline__ void ldsm_x4_t(uint32_t addr, uint32_t& r0, uint32_t& r1,
                                          uint32_t& r2, uint32_t& r3) {
    asm volatile("ldmatrix.sync.aligned.m8n8.x4.trans.shared.b16 {%0,%1,%2,%3}, [%4];"
                 : "=r"(r0), "=r"(r1), "=r"(r2), "=r"(r3) : "r"(addr));
}

__device__ __forceinline__ void mma16816(float* c, const uint32_t* a, uint32_t b0, uint32_t b1) {
    asm volatile(
        "mma.sync.aligned.m16n8k16.row.col.f32.f16.f16.f32 "
        "{%0,%1,%2,%3}, {%4,%5,%6,%7}, {%8,%9}, {%0,%1,%2,%3};"
        : "+f"(c[0]), "+f"(c[1]), "+f"(c[2]), "+f"(c[3])
        : "r"(a[0]), "r"(a[1]), "r"(a[2]), "r"(a[3]), "r"(b0), "r"(b1));
}

__device__ __forceinline__ uint32_t pack_h2(float x, float y) {
    __half2 h = __floats2half2_rn(x, y);
    return *reinterpret_cast<uint32_t*>(&h);
}

__device__ __forceinline__ float ex2f(float x) {
    float y;
    asm("ex2.approx.ftz.f32 %0, %1;" : "=f"(y) : "f"(x));
    return y;
}

__device__ __forceinline__ void cp16(uint32_t dst_smem, const void* src) {
    asm volatile("cp.async.cg.shared.global [%0], [%1], 16;" :: "r"(dst_smem), "l"(src));
}
#define CP_COMMIT() asm volatile("cp.async.commit_group;")
#define CP_WAIT1()  asm volatile("cp.async.wait_group 1;")

// ---------------- merged f32 -> f16 convert (q, in_w, out_w; 2 chunks/thread)
__device__ __forceinline__ void f2h_one(const float4* __restrict__ q,
                                        const float4* __restrict__ wi,
                                        const float4* __restrict__ wo,
                                        __half* __restrict__ q16,
                                        __half* __restrict__ wi16,
                                        __half* __restrict__ wo16, int i) {
    const float4* src;
    __half* dst;
    int j;
    if (i < Q4)            { src = q;  dst = q16;  j = i; }
    else if (i < Q4 + WI4) { src = wi; dst = wi16; j = i - Q4; }
    else                   { src = wo; dst = wo16; j = i - Q4 - WI4; }
    float4 f = src[j];
    __half2* d = (__half2*)(dst + (size_t)j * 4);
    d[0] = __floats2half2_rn(f.x, f.y);
    d[1] = __floats2half2_rn(f.z, f.w);
}

__global__ void f2h_all_kernel(const float4* __restrict__ q,
                               const float4* __restrict__ wi,
                               const float4* __restrict__ wo,
                               __half* __restrict__ q16,
                               __half* __restrict__ wi16,
                               __half* __restrict__ wo16) {
    const int span = gridDim.x * blockDim.x;     // TOT4/2
    int i0 = blockIdx.x * blockDim.x + threadIdx.x;
    // two independent chunks per thread -> 2 LDG.128 in flight (MLP=2)
    if (i0 < TOT4) f2h_one(q, wi, wo, q16, wi16, wo16, i0);
    int i1 = i0 + span;
    if (i1 < TOT4) f2h_one(q, wi, wo, q16, wi16, wo16, i1);
}

// ---------------------------------------------------------------------------
// GEMM: C[M,N] = A16[M,K] @ W16[N,K]^T + bias.  128x128 tile, BK=64,
// 256 threads = 8 warps (2m x 4n), warp tile 64x32, mma.m16n8k16.
// 3-stage cp.async pipeline; smem = 3 * 32 KB = 96 KB dynamic.
// ---------------------------------------------------------------------------
template <bool OUT_HALF>
__global__ __launch_bounds__(256, 2) void gemm16_kernel(
    const __half* __restrict__ A, const __half* __restrict__ W,
    const float* __restrict__ bias, void* __restrict__ Cout,
    int M, int N, int K)
{
    extern __shared__ __half sm[];
    const int tid = threadIdx.x;
    const int lane = tid & 31, wid = tid >> 5;
    const int wm = wid >> 2, wn = wid & 3;
    const int m0 = blockIdx.y * 128, n0 = blockIdx.x * 128;

    float acc[4][4][4];
#pragma unroll
    for (int i = 0; i < 4; i++)
#pragma unroll
        for (int j = 0; j < 4; j++)
#pragma unroll
            for (int r = 0; r < 4; r++) acc[i][j][r] = 0.0f;

    auto prefetch = [&](int k0, int s) {
#pragma unroll
        for (int i = 0; i < 4; i++) {
            int cid = tid + 256 * i;       // 0..1023
            int row = cid >> 3;            // 0..127
            int ch  = cid & 7;             // 0..7
            int sw  = (ch ^ (row & 7)) * 8;
            cp16(smem_u32(sm + s * 8192 + row * 64 + sw),
                 A + (size_t)(m0 + row) * K + k0 + ch * 8);
            cp16(smem_u32(sm + 24576 + s * 8192 + row * 64 + sw),
                 W + (size_t)(n0 + row) * K + k0 + ch * 8);
        }
    };

    const int nk = K / 64;
    prefetch(0, 0); CP_COMMIT();
    prefetch(64, 1); CP_COMMIT();

    for (int t = 0; t < nk; t++) {
        CP_WAIT1();
        __syncthreads();
        if (t + 2 < nk) prefetch((t + 2) * 64, (t + 2) % 3);
        CP_COMMIT();

        const __half* As = sm + (t % 3) * 8192;
        const __half* Bs = sm + 24576 + (t % 3) * 8192;

#pragma unroll
        for (int ks = 0; ks < 4; ks++) {
            uint32_t a[4][4];
#pragma unroll
            for (int mt = 0; mt < 4; mt++) {
                int row = wm * 64 + mt * 16 + (lane & 15);
                int kk = ks * 16 + (lane >> 4) * 8;
                int ch = (kk >> 3) ^ (row & 7);
                ldsm_x4(smem_u32(As + row * 64 + ch * 8), a[mt][0], a[mt][1], a[mt][2], a[mt][3]);
            }
#pragma unroll
            for (int ntp = 0; ntp < 2; ntp++) {
                int row = wn * 32 + ntp * 16 + ((lane >> 4) & 1) * 8 + (lane & 7);
                int kk = ks * 16 + ((lane >> 3) & 1) * 8;
                int ch = (kk >> 3) ^ (row & 7);
                uint32_t b0, b1, b2, b3;
                ldsm_x4(smem_u32(Bs + row * 64 + ch * 8), b0, b1, b2, b3);
#pragma unroll
                for (int mt = 0; mt < 4; mt++) {
                    mma16816(acc[mt][2 * ntp], a[mt], b0, b1);
                    mma16816(acc[mt][2 * ntp + 1], a[mt], b2, b3);
                }
            }
        }
    }

    // epilogue
    const int g = lane >> 2, qd = lane & 3;
#pragma unroll
    for (int mt = 0; mt < 4; mt++) {
#pragma unroll
        for (int nt = 0; nt < 4; nt++) {
            int row = m0 + wm * 64 + mt * 16 + g;
            int col = n0 + wn * 32 + nt * 8 + 2 * qd;
            float b0 = bias[col], b1 = bias[col + 1];
            float v0 = acc[mt][nt][0] + b0, v1 = acc[mt][nt][1] + b1;
            float v2 = acc[mt][nt][2] + b0, v3 = acc[mt][nt][3] + b1;
            if (OUT_HALF) {
                float qs = (col < EMB) ? Q_PRESCALE : 1.0f;   // Q columns of QKV
                v0 *= qs; v1 *= qs; v2 *= qs; v3 *= qs;
                __half* C = (__half*)Cout;
                *(__half2*)(C + (size_t)row * N + col) = __floats2half2_rn(v0, v1);
                *(__half2*)(C + (size_t)(row + 8) * N + col) = __floats2half2_rn(v2, v3);
            } else {
                float* C = (float*)Cout;
                *(float2*)(C + (size_t)row * N + col) = make_float2(v0, v1);
                *(float2*)(C + (size_t)(row + 8) * N + col) = make_float2(v2, v3);
            }
        }
    }
}

// ---------------------------------------------------------------------------
// Fused attention: block = (q-tile of 128, one (b,h)).  8 warps x 16 q-rows.
// Q pre-scaled by 0.125*log2e -> QK^T accumulators are log2-domain scores.
// pass1: s_row = sum ex2(acc);  pass2: w = ex2(acc - log2(s_row)) -> P@V.
// Weight stores predicated on write_w (dead-store elimination when scratch).
// 3-stage cp.async ring; startup prefetches overlapped with LDSM/reduction.
// smem: Q 16KB + 3x8KB K + 3x8KB V = 64 KB.
// ---------------------------------------------------------------------------
__global__ __launch_bounds__(256, 2) void attn16_kernel(
    const __half* __restrict__ qkv, float* __restrict__ attnw,
    __half* __restrict__ aout, int write_w)
{
    extern __shared__ __half sm[];
    __half* Qs = sm;                 // [128][64]
    __half* KsB = sm + 8192;         // 3 x [64][64]
    __half* VsB = sm + 20480;        // 3 x [64][64]

    const int tid = threadIdx.x;
    const int lane = tid & 31, wid = tid >> 5;
    const int qt = blockIdx.x, bh = blockIdx.y;
    const int b = bh >> 4, h = bh & 15;
    const int rowbase = b * S_LEN;
    const int q0 = qt * 128;
    const int stride = 3 * EMB;
    const int g = lane >> 2, qd = lane & 3;
    const int NJT = S_LEN / 64;

    auto pre_k = [&](int jt, int s) {
#pragma unroll
        for (int i = 0; i < 2; i++) {
            int cid = tid + 256 * i;
            int row = cid >> 3, ch = cid & 7;
            cp16(smem_u32(KsB + s * 4096 + row * 64 + (ch ^ (row & 7)) * 8),
                 qkv + (size_t)(rowbase + jt * 64 + row) * stride + EMB + h * HDIM + ch * 8);
        }
    };
    auto pre_kv = [&](int jt, int s) {
#pragma unroll
        for (int i = 0; i < 2; i++) {
            int cid = tid + 256 * i;
            int row = cid >> 3, ch = cid & 7;
            const __half* src = qkv + (size_t)(rowbase + jt * 64 + row) * stride + h * HDIM + ch * 8;
            uint32_t sw = (ch ^ (row & 7)) * 8;
            cp16(smem_u32(KsB + s * 4096 + row * 64 + sw), src + EMB);
            cp16(smem_u32(VsB + s * 4096 + row * 64 + sw), src + 2 * EMB);
        }
    };

    // load Q tile (128 x 64 halves), swizzled
#pragma unroll
    for (int i = 0; i < 4; i++) {
        int cid = tid + 256 * i;
        int row = cid >> 3, ch = cid & 7;
        *(uint4*)&Qs[row * 64 + (ch ^ (row & 7)) * 8] =
            *(const uint4*)(qkv + (size_t)(rowbase + q0 + row) * stride + h * HDIM + ch * 8);
    }
    __syncthreads();

    // issue first two K-stage prefetches BEFORE the Q-frag LDSM (overlap)
    pre_k(0, 0); CP_COMMIT();
    pre_k(1, 1); CP_COMMIT();

    // Q fragments (persist across both passes)
    uint32_t qa[4][4];
#pragma unroll
    for (int ks = 0; ks < 4; ks++) {
        int row = wid * 16 + (lane & 15);
        int kk = ks * 16 + (lane >> 4) * 8;
        int ch = (kk >> 3) ^ (row & 7);
        ldsm_x4(smem_u32(Qs + row * 64 + ch * 8), qa[ks][0], qa[ks][1], qa[ks][2], qa[ks][3]);
    }

    float s0r = 0.0f, s1r = 0.0f;

    // ---------------- pass 1: denominators ----------------
    for (int jt = 0; jt < NJT; jt++) {
        CP_WAIT1();
        __syncthreads();
        if (jt + 2 < NJT) pre_k(jt + 2, (jt + 2) % 3);
        CP_COMMIT();
        const __half* Ks = KsB + (jt % 3) * 4096;

        float sc[8][4];
#pragma unroll
        for (int t = 0; t < 8; t++)
#pragma unroll
            for (int r = 0; r < 4; r++) sc[t][r] = 0.0f;

#pragma unroll
        for (int ks = 0; ks < 4; ks++) {
#pragma unroll
            for (int ntp = 0; ntp < 4; ntp++) {
                int row = ntp * 16 + ((lane >> 4) & 1) * 8 + (lane & 7);
                int kk = ks * 16 + ((lane >> 3) & 1) * 8;
                int ch = (kk >> 3) ^ (row & 7);
                uint32_t b0, b1, b2, b3;
                ldsm_x4(smem_u32(Ks + row * 64 + ch * 8), b0, b1, b2, b3);
                mma16816(sc[2 * ntp], qa[ks], b0, b1);
                mma16816(sc[2 * ntp + 1], qa[ks], b2, b3);
            }
        }

        float p0 = 0.0f, p1 = 0.0f;
#pragma unroll
        for (int t = 0; t < 8; t++) {
            p0 += ex2f(sc[t][0]) + ex2f(sc[t][1]);
            p1 += ex2f(sc[t][2]) + ex2f(sc[t][3]);
        }
        s0r += p0;
        s1r += p1;
    }

    // stage 0 was last read at jt=30 (all warps past it via the jt=31 sync):
    // prefetch pass-2 tile 0 NOW, overlapping the reduction + log2 below.
    pre_kv(0, 0); CP_COMMIT();

    s0r += __shfl_xor_sync(0xffffffffu, s0r, 1);
    s0r += __shfl_xor_sync(0xffffffffu, s0r, 2);
    s1r += __shfl_xor_sync(0xffffffffu, s1r, 1);
    s1r += __shfl_xor_sync(0xffffffffu, s1r, 2);

    const float c0 = -__log2f(s0r);
    const float c1 = -__log2f(s1r);

    // stage 1 was read at jt=31: all warps must be done before overwriting.
    __syncthreads();
    pre_kv(1, 1); CP_COMMIT();

    // ---------------- pass 2: weights + P@V ----------------
    float oacc[8][4];
#pragma unroll
    for (int t = 0; t < 8; t++)
#pragma unroll
        for (int r = 0; r < 4; r++) oacc[t][r] = 0.0f;

    float* wbase0 = attnw + ((size_t)bh * S_LEN + q0 + wid * 16) * S_LEN;

    for (int jt = 0; jt < NJT; jt++) {
        CP_WAIT1();
        __syncthreads();
        if (jt + 2 < NJT) pre_kv(jt + 2, (jt + 2) % 3);
        CP_COMMIT();
        const __half* Ks = KsB + (jt % 3) * 4096;
        const __half* Vs = VsB + (jt % 3) * 4096;

        float sc[8][4];
#pragma unroll
        for (int t = 0; t < 8; t++)
#pragma unroll
            for (int r = 0; r < 4; r++) sc[t][r] = 0.0f;

#pragma unroll
        for (int ks = 0; ks < 4; ks++) {
#pragma unroll
            for (int ntp = 0; ntp < 4; ntp++) {
                int row = ntp * 16 + ((lane >> 4) & 1) * 8 + (lane & 7);
                int kk = ks * 16 + ((lane >> 3) & 1) * 8;
                int ch = (kk >> 3) ^ (row & 7);
                uint32_t b0, b1, b2, b3;
                ldsm_x4(smem_u32(Ks + row * 64 + ch * 8), b0, b1, b2, b3);
                mma16816(sc[2 * ntp], qa[ks], b0, b1);
                mma16816(sc[2 * ntp + 1], qa[ks], b2, b3);
            }
        }

        // normalized weights: f32 streaming store (if live) + f16 A-frag pack
        uint32_t pa[4][4];
#pragma unroll
        for (int t = 0; t < 8; t++) {
            float w0 = ex2f(sc[t][0] + c0);
            float w1 = ex2f(sc[t][1] + c0);
            float w2 = ex2f(sc[t][2] + c1);
            float w3 = ex2f(sc[t][3] + c1);
            if (write_w) {
                float* wp = wbase0 + (size_t)g * S_LEN + jt * 64 + t * 8 + 2 * qd;
                __stcs((float2*)wp, make_float2(w0, w1));
                __stcs((float2*)(wp + 8 * S_LEN), make_float2(w2, w3));
            }
            pa[t >> 1][(t & 1) * 2 + 0] = pack_h2(w0, w1);
            pa[t >> 1][(t & 1) * 2 + 1] = pack_h2(w2, w3);
        }

        // P @ V
#pragma unroll
        for (int ks2 = 0; ks2 < 4; ks2++) {
#pragma unroll
            for (int dtp = 0; dtp < 4; dtp++) {
                int jrow = ks2 * 16 + ((lane >> 3) & 1) * 8 + (lane & 7);
                int dt = dtp * 2 + ((lane >> 4) & 1);
                int ch = dt ^ (jrow & 7);
                uint32_t b0, b1, b2, b3;
                ldsm_x4_t(smem_u32(Vs + jrow * 64 + ch * 8), b0, b1, b2, b3);
                mma16816(oacc[2 * dtp], pa[ks2], b0, b1);
                mma16816(oacc[2 * dtp + 1], pa[ks2], b2, b3);
            }
        }
    }

    // write attn_out (f16, [B*S, E], head slice)
#pragma unroll
    for (int dt = 0; dt < 8; dt++) {
        int row = rowbase + q0 + wid * 16 + g;
        int col = h * HDIM + dt * 8 + 2 * qd;
        *(__half2*)(aout + (size_t)row * EMB + col) = __floats2half2_rn(oacc[dt][0], oacc[dt][1]);
        *(__half2*)(aout + (size_t)(row + 8) * EMB + col) = __floats2half2_rn(oacc[dt][2], oacc[dt][3]);
    }
}

// ---------------------------------------------------------------------------
extern "C" void kernel_launch(void* const* d_in, const int* in_sizes, int n_in,
                              void* d_out, int out_size)
{
    const float* query = (const float*)d_in[0];
    const float* in_w  = (const float*)d_in[3];
    const float* in_b  = (const float*)d_in[4];
    const float* out_w = (const float*)d_in[5];
    const float* out_b = (const float*)d_in[6];
    float* out = (float*)d_out;

    __half *q16, *wi16, *wo16, *qkv16, *ao16;
    float* wfall;
    cudaGetSymbolAddress((void**)&q16, g_q16);
    cudaGetSymbolAddress((void**)&wi16, g_wi16);
    cudaGetSymbolAddress((void**)&wo16, g_wo16);
    cudaGetSymbolAddress((void**)&qkv16, g_qkv16);
    cudaGetSymbolAddress((void**)&ao16, g_ao16);
    cudaGetSymbolAddress((void**)&wfall, g_attnw_fallback);

    const int weights_live = ((size_t)out_size >= (size_t)OUT_ELEMS + W_ELEMS) ? 1 : 0;
    float* attnw = weights_live ? (out + OUT_ELEMS) : wfall;

    cudaFuncSetAttribute(gemm16_kernel<true>, cudaFuncAttributeMaxDynamicSharedMemorySize, 98304);
    cudaFuncSetAttribute(gemm16_kernel<false>, cudaFuncAttributeMaxDynamicSharedMemorySize, 98304);
    cudaFuncSetAttribute(attn16_kernel, cudaFuncAttributeMaxDynamicSharedMemorySize, 65536);

    // merged f32 -> f16 convert, 2 chunks per thread (MLP=2)
    const int f2h_threads = (TOT4 + 1) / 2;
    f2h_all_kernel<<<(f2h_threads + 255) / 256, 256>>>(
        (const float4*)query, (const float4*)in_w, (const float4*)out_w,
        q16, wi16, wo16);

    // QKV projection -> f16 (Q columns pre-scaled to log2 domain)
    gemm16_kernel<true><<<dim3(3 * EMB / 128, MROWS / 128), 256, 98304>>>(
        q16, wi16, in_b, qkv16, MROWS, 3 * EMB, EMB);

    // fused attention (weights f32 only when live + attn_out f16)
    attn16_kernel<<<dim3(S_LEN / 128, BATCH * NHEAD), 256, 65536>>>(
        qkv16, attnw, ao16, weights_live);

    // output projection -> f32
    gemm16_kernel<false><<<dim3(EMB / 128, MROWS / 128), 256, 98304>>>(
        ao16, wo16, out_b, out, MROWS, EMB, EMB);
}